// round 2
// baseline (speedup 1.0000x reference)
#include <cuda_runtime.h>
#include <math.h>

// Problem constants
#define SEQ    512
#define BATCH  64
#define H2     1024
#define DIN    3072
#define KST    2048                 // state part of concat (2 layers * 1024)
#define M_ROWS (SEQ * BATCH)        // 32768 rows of enc, row m = s*64 + b
#define NT     16                   // 1024 / BN n-tiles in energy GEMM
#define KSPLIT 8                    // split-K for the tiny u GEMM

// GEMM tiling
#define BM 64
#define BN 64
#define BK 16

// Scratch (static device arrays; no dynamic allocation allowed)
__device__ __align__(16) float g_st[BATCH * KST];              // 512 KB: state flattened (b, l*1024+k)
__device__ __align__(16) float g_upart[KSPLIT * BATCH * H2];   // 2 MB: split-K partials of u
__device__ __align__(16) float g_u[BATCH * H2];                // 256 KB: u[b][h] = W1_state . st_b + b1
__device__ __align__(16) float g_epart[NT * M_ROWS];           // 2 MB: per-nTile partial energies

// ---------------------------------------------------------------------------
// Kernel 0: gather state (2,64,1024) -> st (64, 2048) with d = l*1024 + k
// ---------------------------------------------------------------------------
__global__ void buildSt(const float* __restrict__ state) {
    int idx = blockIdx.x * blockDim.x + threadIdx.x;   // 0 .. 131071
    int k = idx & 1023;
    int b = (idx >> 10) & 63;
    int l = idx >> 16;
    g_st[b * KST + l * 1024 + k] = state[(l * 64 + b) * 1024 + k];
}

// ---------------------------------------------------------------------------
// Kernel 1: u partials.  C[b][h] = sum_k st[b][k] * W1[h][k], split over K.
// grid = (16 nTiles, 8 ksplits), 256 threads.
// ---------------------------------------------------------------------------
__global__ void uGemm(const float* __restrict__ W1) {
    const int n0 = blockIdx.x * BN;
    const int ks = blockIdx.y;
    const int k0base = ks * (KST / KSPLIT);   // 256-wide K slice

    __shared__ float As[BK][BM];
    __shared__ float Bs[BK][BN];

    const int tid = threadIdx.x;
    const int tx = tid & 15;
    const int ty = tid >> 4;
    const int lrow = tid >> 2;          // 0..63
    const int lcol = (tid & 3) * 4;     // 0,4,8,12

    float acc[4][4];
#pragma unroll
    for (int i = 0; i < 4; i++)
#pragma unroll
        for (int j = 0; j < 4; j++) acc[i][j] = 0.f;

    for (int k0 = k0base; k0 < k0base + (KST / KSPLIT); k0 += BK) {
        float4 a = *(const float4*)&g_st[lrow * KST + k0 + lcol];
        float4 w = *(const float4*)&W1[(n0 + lrow) * DIN + k0 + lcol];
        As[lcol + 0][lrow] = a.x; As[lcol + 1][lrow] = a.y;
        As[lcol + 2][lrow] = a.z; As[lcol + 3][lrow] = a.w;
        Bs[lcol + 0][lrow] = w.x; Bs[lcol + 1][lrow] = w.y;
        Bs[lcol + 2][lrow] = w.z; Bs[lcol + 3][lrow] = w.w;
        __syncthreads();
#pragma unroll
        for (int kk = 0; kk < BK; kk++) {
            float4 av = *(const float4*)&As[kk][ty * 4];
            float4 bv = *(const float4*)&Bs[kk][tx * 4];
            acc[0][0] += av.x * bv.x; acc[0][1] += av.x * bv.y; acc[0][2] += av.x * bv.z; acc[0][3] += av.x * bv.w;
            acc[1][0] += av.y * bv.x; acc[1][1] += av.y * bv.y; acc[1][2] += av.y * bv.z; acc[1][3] += av.y * bv.w;
            acc[2][0] += av.z * bv.x; acc[2][1] += av.z * bv.y; acc[2][2] += av.z * bv.z; acc[2][3] += av.z * bv.w;
            acc[3][0] += av.w * bv.x; acc[3][1] += av.w * bv.y; acc[3][2] += av.w * bv.z; acc[3][3] += av.w * bv.w;
        }
        __syncthreads();
    }

    float* dst = &g_upart[ks * (BATCH * H2)];
#pragma unroll
    for (int i = 0; i < 4; i++) {
        int b = ty * 4 + i;
#pragma unroll
        for (int j = 0; j < 4; j++) {
            int h = n0 + tx * 4 + j;
            dst[b * H2 + h] = acc[i][j];
        }
    }
}

// ---------------------------------------------------------------------------
// Kernel 2: reduce split-K partials + bias -> g_u
// ---------------------------------------------------------------------------
__global__ void reduceU(const float* __restrict__ b1) {
    int idx = blockIdx.x * blockDim.x + threadIdx.x;   // 0 .. 65535
    int h = idx & 1023;
    float s = b1[h];
#pragma unroll
    for (int ks = 0; ks < KSPLIT; ks++) s += g_upart[ks * (BATCH * H2) + idx];
    g_u[idx] = s;
}

// ---------------------------------------------------------------------------
// Kernel 3 (the big one): per n-tile partial energy.
// z[m][n] = sum_k enc[m][k] * W1enc[n][k]     (m = s*64+b ; tile rows <=> b)
// epart[nTile][m] = sum_{n in tile} W2[n] * tanh(z + u[b][n])
// grid = (512 mTiles, 16 nTiles), 256 threads.
// ---------------------------------------------------------------------------
__global__ void energyGemm(const float* __restrict__ enc,
                           const float* __restrict__ W1,
                           const float* __restrict__ W2) {
    const int m0 = blockIdx.x * BM;     // rows m0..m0+63 : s = blockIdx.x, b = row
    const int n0 = blockIdx.y * BN;

    __shared__ float As[BK][BM];
    __shared__ float Bs[BK][BN];
    __shared__ float red[BM][16];

    const int tid = threadIdx.x;
    const int tx = tid & 15;
    const int ty = tid >> 4;
    const int lrow = tid >> 2;
    const int lcol = (tid & 3) * 4;

    float acc[4][4];
#pragma unroll
    for (int i = 0; i < 4; i++)
#pragma unroll
        for (int j = 0; j < 4; j++) acc[i][j] = 0.f;

    for (int k0 = 0; k0 < H2; k0 += BK) {
        float4 a = *(const float4*)&enc[(m0 + lrow) * H2 + k0 + lcol];
        float4 w = *(const float4*)&W1[(n0 + lrow) * DIN + KST + k0 + lcol];
        As[lcol + 0][lrow] = a.x; As[lcol + 1][lrow] = a.y;
        As[lcol + 2][lrow] = a.z; As[lcol + 3][lrow] = a.w;
        Bs[lcol + 0][lrow] = w.x; Bs[lcol + 1][lrow] = w.y;
        Bs[lcol + 2][lrow] = w.z; Bs[lcol + 3][lrow] = w.w;
        __syncthreads();
#pragma unroll
        for (int kk = 0; kk < BK; kk++) {
            float4 av = *(const float4*)&As[kk][ty * 4];
            float4 bv = *(const float4*)&Bs[kk][tx * 4];
            acc[0][0] += av.x * bv.x; acc[0][1] += av.x * bv.y; acc[0][2] += av.x * bv.z; acc[0][3] += av.x * bv.w;
            acc[1][0] += av.y * bv.x; acc[1][1] += av.y * bv.y; acc[1][2] += av.y * bv.z; acc[1][3] += av.y * bv.w;
            acc[2][0] += av.z * bv.x; acc[2][1] += av.z * bv.y; acc[2][2] += av.z * bv.z; acc[2][3] += av.z * bv.w;
            acc[3][0] += av.w * bv.x; acc[3][1] += av.w * bv.y; acc[3][2] += av.w * bv.z; acc[3][3] += av.w * bv.w;
        }
        __syncthreads();
    }

    // Epilogue: tanh + W2 dot, reduce the 16 column-groups per row.
    float w2f[4];
    int nbase = n0 + tx * 4;
#pragma unroll
    for (int j = 0; j < 4; j++) w2f[j] = W2[nbase + j];

#pragma unroll
    for (int i = 0; i < 4; i++) {
        int row = ty * 4 + i;            // == b
        const float* urow = &g_u[row * H2 + nbase];
        float p = 0.f;
#pragma unroll
        for (int j = 0; j < 4; j++) {
            float z = tanhf(acc[i][j] + urow[j]);
            p += z * w2f[j];
        }
        red[row][tx] = p;
    }
    __syncthreads();

    if (tid < BM) {
        float s = 0.f;
#pragma unroll
        for (int j = 0; j < 16; j++) s += red[tid][j];
        g_epart[blockIdx.y * M_ROWS + m0 + tid] = s;
    }
}

// ---------------------------------------------------------------------------
// Kernel 4: softmax over s per batch.  Writes alpha into d_out[65536 + b*512 + s].
// (b2 is a constant shift -> softmax invariant -> dropped.)
// ---------------------------------------------------------------------------
__global__ void softmaxK(float* __restrict__ out) {
    int b = blockIdx.x;
    int s = threadIdx.x;   // 512 threads
    float e = 0.f;
#pragma unroll
    for (int nt = 0; nt < NT; nt++) e += g_epart[nt * M_ROWS + s * 64 + b];

    __shared__ float sm[512];
    sm[s] = e;
    __syncthreads();
    for (int off = 256; off > 0; off >>= 1) {
        if (s < off) sm[s] = fmaxf(sm[s], sm[s + off]);
        __syncthreads();
    }
    float mx = sm[0];
    __syncthreads();

    float ex = expf(e - mx);
    sm[s] = ex;
    __syncthreads();
    for (int off = 256; off > 0; off >>= 1) {
        if (s < off) sm[s] += sm[s + off];
        __syncthreads();
    }
    float total = sm[0];

    out[BATCH * H2 + b * SEQ + s] = ex / total;
}

// ---------------------------------------------------------------------------
// Kernel 5: context[b][h] = sum_s alpha[b][s] * enc[s][b][h]
// grid = (4 h-chunks, 64 b), 256 threads.
// ---------------------------------------------------------------------------
__global__ void contextK(const float* __restrict__ enc, float* __restrict__ out) {
    int b = blockIdx.y;
    int h = blockIdx.x * 256 + threadIdx.x;

    __shared__ float sa[512];
    sa[threadIdx.x]       = out[BATCH * H2 + b * SEQ + threadIdx.x];
    sa[threadIdx.x + 256] = out[BATCH * H2 + b * SEQ + threadIdx.x + 256];
    __syncthreads();

    const float* base = enc + b * H2 + h;
    float a0 = 0.f, a1 = 0.f, a2 = 0.f, a3 = 0.f;
#pragma unroll 4
    for (int s = 0; s < SEQ; s += 4) {
        a0 += sa[s + 0] * base[(size_t)(s + 0) * (BATCH * H2)];
        a1 += sa[s + 1] * base[(size_t)(s + 1) * (BATCH * H2)];
        a2 += sa[s + 2] * base[(size_t)(s + 2) * (BATCH * H2)];
        a3 += sa[s + 3] * base[(size_t)(s + 3) * (BATCH * H2)];
    }
    out[b * H2 + h] = (a0 + a1) + (a2 + a3);
}

// ---------------------------------------------------------------------------
extern "C" void kernel_launch(void* const* d_in, const int* in_sizes, int n_in,
                              void* d_out, int out_size) {
    const float* state = (const float*)d_in[0];   // (2, 64, 1024)
    const float* enc   = (const float*)d_in[1];   // (512, 64, 1024)
    const float* W1    = (const float*)d_in[2];   // (1024, 3072)
    const float* b1    = (const float*)d_in[3];   // (1024,)
    const float* W2    = (const float*)d_in[4];   // (1, 1024)
    // d_in[5] = b2 : softmax-invariant, unused.
    float* out = (float*)d_out;                   // [0,65536): context ; [65536,98304): alpha

    buildSt<<<512, 256>>>(state);
    uGemm<<<dim3(16, KSPLIT), 256>>>(W1);
    reduceU<<<256, 256>>>(b1);
    energyGemm<<<dim3(M_ROWS / BM, NT), 256>>>(enc, W1, W2);
    softmaxK<<<BATCH, 512>>>(out);
    contextK<<<dim3(4, BATCH), 256>>>(enc, out);
}

// round 4
// speedup vs baseline: 3.6211x; 3.6211x over previous
#include <cuda_runtime.h>
#include <cuda_bf16.h>
#include <cstdint>
#include <math.h>

// ---------------------------------------------------------------------------
// Problem constants
#define SEQ    512
#define BATCH  64
#define H2     1024
#define DIN    3072
#define KST    2048
#define M_ROWS (SEQ * BATCH)        // 32768
#define NT2    8                    // energy partial slabs (8 n-tiles of 128)
#define KSPLIT 8

// fp32 tiling for the small u GEMM
#define BM 64
#define BN 64
#define BK 16

// Scratch
__device__ __align__(16) float g_st[BATCH * KST];
__device__ __align__(16) float g_upart[KSPLIT * BATCH * H2];
__device__ __align__(16) float g_u[BATCH * H2];
__device__ __align__(16) float g_epart[NT2 * M_ROWS];

// ---------------------------------------------------------------------------
// PTX helpers (base ISA only — compiles for sm_103)
// ---------------------------------------------------------------------------
__device__ __forceinline__ uint32_t smem_u32(const void* p) {
    uint32_t a;
    asm("{ .reg .u64 t; cvta.to.shared.u64 t, %1; cvt.u32.u64 %0, t; }" : "=r"(a) : "l"(p));
    return a;
}
// accurate-enough tanh: 1 - 2/(exp2(2*log2e*x)+1)  (~1e-6 abs error)
__device__ __forceinline__ float tanh_ex(float x) {
    float t; asm("ex2.approx.f32 %0, %1;" : "=f"(t) : "f"(x * 2.8853900817779268f));
    float r; asm("rcp.approx.f32 %0, %1;" : "=f"(r) : "f"(t + 1.0f));
    return fmaf(-2.0f, r, 1.0f);
}

#define CP_ASYNC16(dst, src) \
    asm volatile("cp.async.cg.shared.global [%0], [%1], 16;" :: "r"(dst), "l"(src))
#define CP_COMMIT() asm volatile("cp.async.commit_group;" ::: "memory")
#define CP_WAIT1()  asm volatile("cp.async.wait_group 1;" ::: "memory")
#define CP_WAIT0()  asm volatile("cp.async.wait_group 0;" ::: "memory")

__device__ __forceinline__ void ldsm4(uint32_t* d, uint32_t addr) {
    asm volatile("ldmatrix.sync.aligned.m8n8.x4.shared.b16 {%0,%1,%2,%3}, [%4];"
                 : "=r"(d[0]), "=r"(d[1]), "=r"(d[2]), "=r"(d[3]) : "r"(addr));
}
__device__ __forceinline__ void mma16816(float* d, const uint32_t* a,
                                         uint32_t b0, uint32_t b1) {
    asm volatile("mma.sync.aligned.m16n8k16.row.col.f32.bf16.bf16.f32 "
                 "{%0,%1,%2,%3}, {%4,%5,%6,%7}, {%8,%9}, {%0,%1,%2,%3};"
                 : "+f"(d[0]), "+f"(d[1]), "+f"(d[2]), "+f"(d[3])
                 : "r"(a[0]), "r"(a[1]), "r"(a[2]), "r"(a[3]), "r"(b0), "r"(b1));
}

// ---------------------------------------------------------------------------
// Kernel 0: gather state (2,64,1024) -> st (64, 2048)
// ---------------------------------------------------------------------------
__global__ void buildSt(const float* __restrict__ state) {
    int idx = blockIdx.x * blockDim.x + threadIdx.x;
    int k = idx & 1023;
    int b = (idx >> 10) & 63;
    int l = idx >> 16;
    g_st[b * KST + l * 1024 + k] = state[(l * 64 + b) * 1024 + k];
}

// ---------------------------------------------------------------------------
// Kernel 1: u partials (fp32; tiny)
// ---------------------------------------------------------------------------
__global__ void uGemm(const float* __restrict__ W1) {
    const int n0 = blockIdx.x * BN;
    const int ks = blockIdx.y;
    const int k0base = ks * (KST / KSPLIT);

    __shared__ float As[BK][BM];
    __shared__ float Bs[BK][BN];

    const int tid = threadIdx.x;
    const int tx = tid & 15;
    const int ty = tid >> 4;
    const int lrow = tid >> 2;
    const int lcol = (tid & 3) * 4;

    float acc[4][4];
#pragma unroll
    for (int i = 0; i < 4; i++)
#pragma unroll
        for (int j = 0; j < 4; j++) acc[i][j] = 0.f;

    for (int k0 = k0base; k0 < k0base + (KST / KSPLIT); k0 += BK) {
        float4 a = *(const float4*)&g_st[lrow * KST + k0 + lcol];
        float4 w = *(const float4*)&W1[(n0 + lrow) * DIN + k0 + lcol];
        As[lcol + 0][lrow] = a.x; As[lcol + 1][lrow] = a.y;
        As[lcol + 2][lrow] = a.z; As[lcol + 3][lrow] = a.w;
        Bs[lcol + 0][lrow] = w.x; Bs[lcol + 1][lrow] = w.y;
        Bs[lcol + 2][lrow] = w.z; Bs[lcol + 3][lrow] = w.w;
        __syncthreads();
#pragma unroll
        for (int kk = 0; kk < BK; kk++) {
            float4 av = *(const float4*)&As[kk][ty * 4];
            float4 bv = *(const float4*)&Bs[kk][tx * 4];
            acc[0][0] += av.x * bv.x; acc[0][1] += av.x * bv.y; acc[0][2] += av.x * bv.z; acc[0][3] += av.x * bv.w;
            acc[1][0] += av.y * bv.x; acc[1][1] += av.y * bv.y; acc[1][2] += av.y * bv.z; acc[1][3] += av.y * bv.w;
            acc[2][0] += av.z * bv.x; acc[2][1] += av.z * bv.y; acc[2][2] += av.z * bv.z; acc[2][3] += av.z * bv.w;
            acc[3][0] += av.w * bv.x; acc[3][1] += av.w * bv.y; acc[3][2] += av.w * bv.z; acc[3][3] += av.w * bv.w;
        }
        __syncthreads();
    }

    float* dst = &g_upart[ks * (BATCH * H2)];
#pragma unroll
    for (int i = 0; i < 4; i++) {
        int b = ty * 4 + i;
#pragma unroll
        for (int j = 0; j < 4; j++) dst[b * H2 + n0 + tx * 4 + j] = acc[i][j];
    }
}

// ---------------------------------------------------------------------------
// Kernel 2: reduce split-K partials + bias -> g_u
// ---------------------------------------------------------------------------
__global__ void reduceU(const float* __restrict__ b1) {
    int idx = blockIdx.x * blockDim.x + threadIdx.x;
    int h = idx & 1023;
    float s = b1[h];
#pragma unroll
    for (int ks = 0; ks < KSPLIT; ks++) s += g_upart[ks * (BATCH * H2) + idx];
    g_u[idx] = s;
}

// ---------------------------------------------------------------------------
// Kernel 3: energy GEMM via mma.sync bf16 hi/lo 3-pass + fused tanh/W2 epilogue
//
// CTA 128(M) x 128(N), 256 thr (8 warps: wm=wid>>2 covers 64 rows, wn=wid&3
// covers 32 cols). K chunks of 32 fp32; cp.async double-buffered fp32 staging,
// in-smem split to bf16 hi/lo tiles (swizzled for conflict-free ldmatrix).
//
// SMEM: [0,32K) F0 (fp32 A 16K | B 16K), [32K,64K) F1, [64K,72K) Ah,
//       [72K,80K) Al, [80K,88K) Bh, [88K,96K) Bl.  Total 98304 -> 2 CTA/SM.
// ---------------------------------------------------------------------------
#define EF0    0
#define EF1    32768
#define E_AH   65536
#define E_AL   73728
#define E_BH   81920
#define E_BL   90112
#define EN_SMEM 98304

__device__ __forceinline__ void cvtStore(char* base, int r, int q, float4 v) {
    __nv_bfloat16 h0 = __float2bfloat16(v.x), h1 = __float2bfloat16(v.y);
    __nv_bfloat16 h2 = __float2bfloat16(v.z), h3 = __float2bfloat16(v.w);
    __nv_bfloat162 hA; hA.x = h0; hA.y = h1;
    __nv_bfloat162 hB; hB.x = h2; hB.y = h3;
    __nv_bfloat162 lA, lB;
    lA.x = __float2bfloat16(v.x - __bfloat162float(h0));
    lA.y = __float2bfloat16(v.y - __bfloat162float(h1));
    lB.x = __float2bfloat16(v.z - __bfloat162float(h2));
    lB.y = __float2bfloat16(v.w - __bfloat162float(h3));
    uint32_t off = (uint32_t)(r * 64 + ((((q >> 1) ^ ((r >> 1) & 3)) << 4)) + ((q & 1) << 3));
    *(uint2*)(base + off)        = make_uint2(*(uint32_t*)&hA, *(uint32_t*)&hB);
    *(uint2*)(base + 8192 + off) = make_uint2(*(uint32_t*)&lA, *(uint32_t*)&lB);
}

// ldmatrix address builders (tiles: 128 rows x 32 bf16, 64B rows, XOR swizzle)
__device__ __forceinline__ uint32_t addrA(uint32_t tile, int R, int s, int lane) {
    int r = R + (lane & 15);
    int g = s * 2 + (lane >> 4);
    return tile + r * 64 + ((g ^ ((r >> 1) & 3)) << 4);
}
__device__ __forceinline__ uint32_t addrB(uint32_t tile, int N0, int s, int lane) {
    int n = N0 + (lane & 7) + ((lane >> 4) & 1) * 8;
    int g = s * 2 + ((lane >> 3) & 1);
    return tile + n * 64 + ((g ^ ((n >> 1) & 3)) << 4);
}

__global__ void __launch_bounds__(256, 2)
energyTC(const float* __restrict__ enc,
         const float* __restrict__ W1,
         const float* __restrict__ W2) {
    extern __shared__ char smem[];
    const uint32_t sb = smem_u32(smem);
    const int tid = threadIdx.x;
    const int wid = tid >> 5;
    const int lane = tid & 31;
    const int wm = wid >> 2;      // 0..1
    const int wn = wid & 3;       // 0..3
    const int m0 = blockIdx.x * 128;
    const int n0 = blockIdx.y * 128;

    float acc[4][4][4];
#pragma unroll
    for (int i = 0; i < 4; i++)
#pragma unroll
        for (int j = 0; j < 4; j++)
#pragma unroll
            for (int k = 0; k < 4; k++) acc[i][j][k] = 0.f;

    const int r_ld = tid >> 3;        // 0..31 base row per t-step: r = r_ld + t*32
    const int q_ld = tid & 7;

    // prologue: cp.async chunk 0 -> F0
    {
        const int k0 = 0;
#pragma unroll
        for (int t = 0; t < 4; t++) {
            int r = r_ld + t * 32;
            CP_ASYNC16(sb + EF0 + r * 128 + q_ld * 16,
                       &enc[(size_t)(m0 + r) * H2 + k0 + q_ld * 4]);
            CP_ASYNC16(sb + EF0 + 16384 + r * 128 + q_ld * 16,
                       &W1[(size_t)(n0 + r) * DIN + KST + k0 + q_ld * 4]);
        }
        CP_COMMIT();
    }

    const uint32_t tAh = sb + E_AH, tAl = sb + E_AL;
    const uint32_t tBh = sb + E_BH, tBl = sb + E_BL;

    for (int c = 0; c < 32; c++) {
        if (c < 31) {
            const int k0 = (c + 1) * 32;
            const uint32_t fdst = sb + ((c + 1) & 1 ? EF1 : EF0);
#pragma unroll
            for (int t = 0; t < 4; t++) {
                int r = r_ld + t * 32;
                CP_ASYNC16(fdst + r * 128 + q_ld * 16,
                           &enc[(size_t)(m0 + r) * H2 + k0 + q_ld * 4]);
                CP_ASYNC16(fdst + 16384 + r * 128 + q_ld * 16,
                           &W1[(size_t)(n0 + r) * DIN + KST + k0 + q_ld * 4]);
            }
            CP_COMMIT();
            CP_WAIT1();
        } else {
            CP_WAIT0();
        }
        __syncthreads();

        // convert fp32 stage -> bf16 hi/lo tiles
        {
            char* fp = smem + (c & 1 ? EF1 : EF0);
#pragma unroll
            for (int t = 0; t < 4; t++) {
                int r = r_ld + t * 32;
                float4 va = *(const float4*)(fp + r * 128 + q_ld * 16);
                cvtStore(smem + E_AH, r, q_ld, va);
                float4 vb = *(const float4*)(fp + 16384 + r * 128 + q_ld * 16);
                cvtStore(smem + E_BH, r, q_ld, vb);
            }
        }
        __syncthreads();

        // compute: 2 ksteps x 3 passes (Al*Bh, Ah*Bh, Ah*Bl)
#pragma unroll
        for (int s = 0; s < 2; s++) {
            uint32_t a[4][4], b[2][4];
            // Bh frags (n32 = two n16 ldmatrix)
            ldsm4(b[0], addrB(tBh, wn * 32, s, lane));
            ldsm4(b[1], addrB(tBh, wn * 32 + 16, s, lane));
            // Al
#pragma unroll
            for (int mi = 0; mi < 4; mi++)
                ldsm4(a[mi], addrA(tAl, wm * 64 + mi * 16, s, lane));
#pragma unroll
            for (int mi = 0; mi < 4; mi++)
#pragma unroll
                for (int nj = 0; nj < 4; nj++)
                    mma16816(acc[mi][nj], a[mi], b[nj >> 1][(nj & 1) * 2],
                             b[nj >> 1][(nj & 1) * 2 + 1]);
            // Ah
#pragma unroll
            for (int mi = 0; mi < 4; mi++)
                ldsm4(a[mi], addrA(tAh, wm * 64 + mi * 16, s, lane));
#pragma unroll
            for (int mi = 0; mi < 4; mi++)
#pragma unroll
                for (int nj = 0; nj < 4; nj++)
                    mma16816(acc[mi][nj], a[mi], b[nj >> 1][(nj & 1) * 2],
                             b[nj >> 1][(nj & 1) * 2 + 1]);
            // Bl
            ldsm4(b[0], addrB(tBl, wn * 32, s, lane));
            ldsm4(b[1], addrB(tBl, wn * 32 + 16, s, lane));
#pragma unroll
            for (int mi = 0; mi < 4; mi++)
#pragma unroll
                for (int nj = 0; nj < 4; nj++)
                    mma16816(acc[mi][nj], a[mi], b[nj >> 1][(nj & 1) * 2],
                             b[nj >> 1][(nj & 1) * 2 + 1]);
        }
        __syncthreads();
    }

    // ---- epilogue: stage u[64][128] (pad 132) + w2[128] + red[128][4] in smem
    float* su  = (float*)smem;                 // 64*132*4 = 33792 B
    float* sw2 = (float*)(smem + 33792);       // 512 B
    float* red = (float*)(smem + 34304);       // 2048 B
    for (int i = tid; i < 64 * 128; i += 256) {
        int b = i >> 7, n = i & 127;
        su[b * 132 + n] = g_u[b * H2 + n0 + n];
    }
    if (tid < 128) sw2[tid] = W2[n0 + tid];
    __syncthreads();

    {
        const int g = lane >> 2, t = lane & 3;
        float part[4][2];
#pragma unroll
        for (int mi = 0; mi < 4; mi++) { part[mi][0] = 0.f; part[mi][1] = 0.f; }

#pragma unroll
        for (int mi = 0; mi < 4; mi++) {
            int r_lo = wm * 64 + mi * 16 + g;
            int b_lo = r_lo & 63;
            int b_hi = (r_lo + 8) & 63;
#pragma unroll
            for (int nj = 0; nj < 4; nj++) {
                int n = wn * 32 + nj * 8 + 2 * t;
                float w0 = sw2[n], w1 = sw2[n + 1];
                float z00 = acc[mi][nj][0] + su[b_lo * 132 + n];
                float z01 = acc[mi][nj][1] + su[b_lo * 132 + n + 1];
                float z10 = acc[mi][nj][2] + su[b_hi * 132 + n];
                float z11 = acc[mi][nj][3] + su[b_hi * 132 + n + 1];
                part[mi][0] += w0 * tanh_ex(z00) + w1 * tanh_ex(z01);
                part[mi][1] += w0 * tanh_ex(z10) + w1 * tanh_ex(z11);
            }
        }
#pragma unroll
        for (int o = 1; o <= 2; o <<= 1)
#pragma unroll
            for (int mi = 0; mi < 4; mi++) {
                part[mi][0] += __shfl_xor_sync(0xffffffffu, part[mi][0], o);
                part[mi][1] += __shfl_xor_sync(0xffffffffu, part[mi][1], o);
            }
        if (t == 0) {
#pragma unroll
            for (int mi = 0; mi < 4; mi++) {
                red[(wm * 64 + mi * 16 + g) * 4 + wn]     = part[mi][0];
                red[(wm * 64 + mi * 16 + g + 8) * 4 + wn] = part[mi][1];
            }
        }
    }
    __syncthreads();

    if (tid < 128) {
        float s = red[tid * 4 + 0] + red[tid * 4 + 1] + red[tid * 4 + 2] + red[tid * 4 + 3];
        g_epart[(size_t)blockIdx.y * M_ROWS + m0 + tid] = s;
    }
}

// ---------------------------------------------------------------------------
// Kernel 4: softmax over s per batch -> alpha
// ---------------------------------------------------------------------------
__global__ void softmaxK(float* __restrict__ out) {
    int b = blockIdx.x;
    int s = threadIdx.x;
    float e = 0.f;
#pragma unroll
    for (int nt = 0; nt < NT2; nt++) e += g_epart[nt * M_ROWS + s * 64 + b];

    __shared__ float sm[512];
    sm[s] = e;
    __syncthreads();
    for (int off = 256; off > 0; off >>= 1) {
        if (s < off) sm[s] = fmaxf(sm[s], sm[s + off]);
        __syncthreads();
    }
    float mx = sm[0];
    __syncthreads();

    float ex = expf(e - mx);
    sm[s] = ex;
    __syncthreads();
    for (int off = 256; off > 0; off >>= 1) {
        if (s < off) sm[s] += sm[s + off];
        __syncthreads();
    }
    float total = sm[0];

    out[BATCH * H2 + b * SEQ + s] = ex / total;
}

// ---------------------------------------------------------------------------
// Kernel 5: context[b][h] = sum_s alpha[b][s] * enc[s][b][h]
// ---------------------------------------------------------------------------
__global__ void contextK(const float* __restrict__ enc, float* __restrict__ out) {
    int b = blockIdx.y;
    int h = blockIdx.x * 256 + threadIdx.x;

    __shared__ float sa[512];
    sa[threadIdx.x]       = out[BATCH * H2 + b * SEQ + threadIdx.x];
    sa[threadIdx.x + 256] = out[BATCH * H2 + b * SEQ + threadIdx.x + 256];
    __syncthreads();

    const float* base = enc + b * H2 + h;
    float a0 = 0.f, a1 = 0.f, a2 = 0.f, a3 = 0.f;
#pragma unroll 4
    for (int s = 0; s < SEQ; s += 4) {
        a0 += sa[s + 0] * base[(size_t)(s + 0) * (BATCH * H2)];
        a1 += sa[s + 1] * base[(size_t)(s + 1) * (BATCH * H2)];
        a2 += sa[s + 2] * base[(size_t)(s + 2) * (BATCH * H2)];
        a3 += sa[s + 3] * base[(size_t)(s + 3) * (BATCH * H2)];
    }
    out[b * H2 + h] = (a0 + a1) + (a2 + a3);
}

// ---------------------------------------------------------------------------
extern "C" void kernel_launch(void* const* d_in, const int* in_sizes, int n_in,
                              void* d_out, int out_size) {
    const float* state = (const float*)d_in[0];
    const float* enc   = (const float*)d_in[1];
    const float* W1    = (const float*)d_in[2];
    const float* b1    = (const float*)d_in[3];
    const float* W2    = (const float*)d_in[4];
    float* out = (float*)d_out;

    cudaFuncSetAttribute(energyTC, cudaFuncAttributeMaxDynamicSharedMemorySize, EN_SMEM);

    buildSt<<<512, 256>>>(state);
    uGemm<<<dim3(16, KSPLIT), 256>>>(W1);
    reduceU<<<256, 256>>>(b1);
    energyTC<<<dim3(M_ROWS / 128, 8), 256, EN_SMEM>>>(enc, W1, W2);
    softmaxK<<<BATCH, 512>>>(out);
    contextK<<<dim3(4, BATCH), 256>>>(enc, out);
}

// round 5
// speedup vs baseline: 5.2762x; 1.4571x over previous
#include <cuda_runtime.h>
#include <cuda_fp16.h>
#include <cstdint>
#include <math.h>

// ---------------------------------------------------------------------------
// Problem constants
#define SEQ    512
#define BATCH  64
#define H2     1024
#define DIN    3072
#define KST    2048
#define M_ROWS (SEQ * BATCH)        // 32768
#define NT2    8                    // energy partial slabs (8 n-tiles of 128)
#define KSPLIT 8

// fp32 tiling for the small u GEMM
#define BM 64
#define BN 64
#define BK 16

// Scratch
__device__ __align__(16) float g_upart[KSPLIT * BATCH * H2];
__device__ __align__(16) float g_u[BATCH * H2];
__device__ __align__(16) float g_epart[NT2 * M_ROWS];
__device__ __align__(16) __half g_encH[M_ROWS * H2];   // 64 MB fp16 enc
__device__ __align__(16) __half g_w1H[H2 * H2];        // 2 MB  fp16 hi of W1enc
__device__ __align__(16) __half g_w1L[H2 * H2];        // 2 MB  fp16 lo of W1enc

// ---------------------------------------------------------------------------
// PTX helpers (base ISA only — compiles for sm_103)
// ---------------------------------------------------------------------------
__device__ __forceinline__ uint32_t smem_u32(const void* p) {
    uint32_t a;
    asm("{ .reg .u64 t; cvta.to.shared.u64 t, %1; cvt.u32.u64 %0, t; }" : "=r"(a) : "l"(p));
    return a;
}
// accurate tanh: 1 - 2/(exp2(2*log2e*x)+1)  (~1e-6 abs error)
__device__ __forceinline__ float tanh_ex(float x) {
    float t; asm("ex2.approx.f32 %0, %1;" : "=f"(t) : "f"(x * 2.8853900817779268f));
    float r; asm("rcp.approx.f32 %0, %1;" : "=f"(r) : "f"(t + 1.0f));
    return fmaf(-2.0f, r, 1.0f);
}

#define CP_ASYNC16(dst, src) \
    asm volatile("cp.async.cg.shared.global [%0], [%1], 16;" :: "r"(dst), "l"(src))
#define CP_COMMIT() asm volatile("cp.async.commit_group;" ::: "memory")
#define CP_WAIT1()  asm volatile("cp.async.wait_group 1;" ::: "memory")
#define CP_WAIT0()  asm volatile("cp.async.wait_group 0;" ::: "memory")

__device__ __forceinline__ void ldsm4(uint32_t* d, uint32_t addr) {
    asm volatile("ldmatrix.sync.aligned.m8n8.x4.shared.b16 {%0,%1,%2,%3}, [%4];"
                 : "=r"(d[0]), "=r"(d[1]), "=r"(d[2]), "=r"(d[3]) : "r"(addr));
}
__device__ __forceinline__ void mma16816h(float* d, const uint32_t* a,
                                          uint32_t b0, uint32_t b1) {
    asm volatile("mma.sync.aligned.m16n8k16.row.col.f32.f16.f16.f32 "
                 "{%0,%1,%2,%3}, {%4,%5,%6,%7}, {%8,%9}, {%0,%1,%2,%3};"
                 : "+f"(d[0]), "+f"(d[1]), "+f"(d[2]), "+f"(d[3])
                 : "r"(a[0]), "r"(a[1]), "r"(a[2]), "r"(a[3]), "r"(b0), "r"(b1));
}

// ---------------------------------------------------------------------------
// Kernel A: enc fp32 -> fp16 (row-major 32768 x 1024)
// ---------------------------------------------------------------------------
__global__ void convEnc(const float* __restrict__ enc) {
    int idx = blockIdx.x * blockDim.x + threadIdx.x;      // 8388608 threads
    float4 v = *(const float4*)(enc + (size_t)idx * 4);
    __half2 h01 = __floats2half2_rn(v.x, v.y);
    __half2 h23 = __floats2half2_rn(v.z, v.w);
    *(uint2*)(g_encH + (size_t)idx * 4) =
        make_uint2(*(uint32_t*)&h01, *(uint32_t*)&h23);
}

// ---------------------------------------------------------------------------
// Kernel B: W1enc fp32 -> fp16 hi + lo (1024 x 1024 slice at col offset KST)
// ---------------------------------------------------------------------------
__global__ void convW1(const float* __restrict__ W1) {
    int idx = blockIdx.x * blockDim.x + threadIdx.x;      // 262144 threads
    int n = idx >> 8;
    int k = (idx & 255) * 4;
    float4 v = *(const float4*)(W1 + (size_t)n * DIN + KST + k);
    __half h0 = __float2half_rn(v.x), h1 = __float2half_rn(v.y);
    __half h2 = __float2half_rn(v.z), h3 = __float2half_rn(v.w);
    __half l0 = __float2half_rn(v.x - __half2float(h0));
    __half l1 = __float2half_rn(v.y - __half2float(h1));
    __half l2 = __float2half_rn(v.z - __half2float(h2));
    __half l3 = __float2half_rn(v.w - __half2float(h3));
    __half2 hh0; hh0.x = h0; hh0.y = h1;
    __half2 hh1; hh1.x = h2; hh1.y = h3;
    __half2 ll0; ll0.x = l0; ll0.y = l1;
    __half2 ll1; ll1.x = l2; ll1.y = l3;
    *(uint2*)(g_w1H + (size_t)n * H2 + k) = make_uint2(*(uint32_t*)&hh0, *(uint32_t*)&hh1);
    *(uint2*)(g_w1L + (size_t)n * H2 + k) = make_uint2(*(uint32_t*)&ll0, *(uint32_t*)&ll1);
}

// ---------------------------------------------------------------------------
// Kernel 1: u partials (fp32; tiny).  Reads state directly (l = kd>>10).
// ---------------------------------------------------------------------------
__global__ void uGemm(const float* __restrict__ state, const float* __restrict__ W1) {
    const int n0 = blockIdx.x * BN;
    const int ks = blockIdx.y;
    const int k0base = ks * (KST / KSPLIT);

    __shared__ float As[BK][BM];
    __shared__ float Bs[BK][BN];

    const int tid = threadIdx.x;
    const int tx = tid & 15;
    const int ty = tid >> 4;
    const int lrow = tid >> 2;
    const int lcol = (tid & 3) * 4;

    float acc[4][4];
#pragma unroll
    for (int i = 0; i < 4; i++)
#pragma unroll
        for (int j = 0; j < 4; j++) acc[i][j] = 0.f;

    for (int k0 = k0base; k0 < k0base + (KST / KSPLIT); k0 += BK) {
        int kd = k0 + lcol;
        int l = kd >> 10, kk = kd & 1023;
        float4 a = *(const float4*)&state[((size_t)(l * 64 + lrow)) * 1024 + kk];
        float4 w = *(const float4*)&W1[(size_t)(n0 + lrow) * DIN + kd];
        As[lcol + 0][lrow] = a.x; As[lcol + 1][lrow] = a.y;
        As[lcol + 2][lrow] = a.z; As[lcol + 3][lrow] = a.w;
        Bs[lcol + 0][lrow] = w.x; Bs[lcol + 1][lrow] = w.y;
        Bs[lcol + 2][lrow] = w.z; Bs[lcol + 3][lrow] = w.w;
        __syncthreads();
#pragma unroll
        for (int kk2 = 0; kk2 < BK; kk2++) {
            float4 av = *(const float4*)&As[kk2][ty * 4];
            float4 bv = *(const float4*)&Bs[kk2][tx * 4];
            acc[0][0] += av.x * bv.x; acc[0][1] += av.x * bv.y; acc[0][2] += av.x * bv.z; acc[0][3] += av.x * bv.w;
            acc[1][0] += av.y * bv.x; acc[1][1] += av.y * bv.y; acc[1][2] += av.y * bv.z; acc[1][3] += av.y * bv.w;
            acc[2][0] += av.z * bv.x; acc[2][1] += av.z * bv.y; acc[2][2] += av.z * bv.z; acc[2][3] += av.z * bv.w;
            acc[3][0] += av.w * bv.x; acc[3][1] += av.w * bv.y; acc[3][2] += av.w * bv.z; acc[3][3] += av.w * bv.w;
        }
        __syncthreads();
    }

    float* dst = &g_upart[ks * (BATCH * H2)];
#pragma unroll
    for (int i = 0; i < 4; i++) {
        int b = ty * 4 + i;
#pragma unroll
        for (int j = 0; j < 4; j++) dst[b * H2 + n0 + tx * 4 + j] = acc[i][j];
    }
}

// ---------------------------------------------------------------------------
// Kernel 2: reduce split-K partials + bias -> g_u
// ---------------------------------------------------------------------------
__global__ void reduceU(const float* __restrict__ b1) {
    int idx = blockIdx.x * blockDim.x + threadIdx.x;
    int h = idx & 1023;
    float s = b1[h];
#pragma unroll
    for (int ks = 0; ks < KSPLIT; ks++) s += g_upart[ks * (BATCH * H2) + idx];
    g_u[idx] = s;
}

// ---------------------------------------------------------------------------
// Kernel 3: energy GEMM, fp16 asymmetric 2-pass (Ah*Bh + Ah*Bl), fused epilogue.
//
// CTA 128(M) x 128(N), 8 warps (2m x 4n), warp tile 64x32.
// K chunks of 64 fp16; double-buffered cp.async of PRECONVERTED fp16 tiles.
// Tiles: [128 rows][64 halfs] = 128B rows, swizzle group g^(r&7).
// Stage = A(16K) + Bh(16K) + Bl(16K) = 48K; 2 stages = 96K -> 2 CTA/SM.
// ---------------------------------------------------------------------------
#define ST_A   0
#define ST_BH  16384
#define ST_BL  32768
#define ST_SZ  49152
#define EN_SMEM 98304

__device__ __forceinline__ uint32_t addrA(uint32_t tile, int R, int s, int lane) {
    int r = R + (lane & 15);
    int g = s * 2 + (lane >> 4);
    return tile + r * 128 + ((g ^ (r & 7)) << 4);
}
__device__ __forceinline__ uint32_t addrB(uint32_t tile, int N0, int s, int lane) {
    int n = N0 + (lane & 7) + ((lane >> 4) & 1) * 8;
    int g = s * 2 + ((lane >> 3) & 1);
    return tile + n * 128 + ((g ^ (n & 7)) << 4);
}

__global__ void __launch_bounds__(256, 2)
energyTC(const float* __restrict__ W2) {
    extern __shared__ char smem[];
    const uint32_t sb = smem_u32(smem);
    const int tid = threadIdx.x;
    const int wid = tid >> 5;
    const int lane = tid & 31;
    const int wm = wid >> 2;      // 0..1
    const int wn = wid & 3;       // 0..3
    const int m0 = blockIdx.x * 128;
    const int n0 = blockIdx.y * 128;

    float acc[4][4][4];
#pragma unroll
    for (int i = 0; i < 4; i++)
#pragma unroll
        for (int j = 0; j < 4; j++)
#pragma unroll
            for (int k = 0; k < 4; k++) acc[i][j][k] = 0.f;

    const int r_ld = tid >> 3;        // base row 0..31; r = r_ld + t*32
    const int g_ld = tid & 7;         // 16B group 0..7

    // stage issue: 12 cp.async per thread (4 A + 4 Bh + 4 Bl)
#define ISSUE(stg, k0)                                                          \
    do {                                                                        \
        uint32_t _s = sb + (stg) * ST_SZ;                                       \
        _Pragma("unroll")                                                       \
        for (int t = 0; t < 4; t++) {                                           \
            int r = r_ld + t * 32;                                              \
            uint32_t sw = ((g_ld ^ (r & 7)) << 4);                              \
            CP_ASYNC16(_s + ST_A + r * 128 + sw,                                \
                       g_encH + (size_t)(m0 + r) * H2 + (k0) + g_ld * 8);       \
            CP_ASYNC16(_s + ST_BH + r * 128 + sw,                               \
                       g_w1H + (size_t)(n0 + r) * H2 + (k0) + g_ld * 8);        \
            CP_ASYNC16(_s + ST_BL + r * 128 + sw,                               \
                       g_w1L + (size_t)(n0 + r) * H2 + (k0) + g_ld * 8);        \
        }                                                                       \
        CP_COMMIT();                                                            \
    } while (0)

    ISSUE(0, 0);
    ISSUE(1, 64);

    for (int c = 0; c < 16; c++) {
        if (c < 15) CP_WAIT1(); else CP_WAIT0();
        __syncthreads();

        const uint32_t stg = sb + (c & 1) * ST_SZ;
        const uint32_t tA = stg + ST_A, tBh = stg + ST_BH, tBl = stg + ST_BL;

#pragma unroll
        for (int s = 0; s < 4; s++) {
            uint32_t a[4][4], b[2][4];
#pragma unroll
            for (int mi = 0; mi < 4; mi++)
                ldsm4(a[mi], addrA(tA, wm * 64 + mi * 16, s, lane));
            // pass hi
            ldsm4(b[0], addrB(tBh, wn * 32, s, lane));
            ldsm4(b[1], addrB(tBh, wn * 32 + 16, s, lane));
#pragma unroll
            for (int mi = 0; mi < 4; mi++)
#pragma unroll
                for (int nj = 0; nj < 4; nj++)
                    mma16816h(acc[mi][nj], a[mi], b[nj >> 1][(nj & 1) * 2],
                              b[nj >> 1][(nj & 1) * 2 + 1]);
            // pass lo
            ldsm4(b[0], addrB(tBl, wn * 32, s, lane));
            ldsm4(b[1], addrB(tBl, wn * 32 + 16, s, lane));
#pragma unroll
            for (int mi = 0; mi < 4; mi++)
#pragma unroll
                for (int nj = 0; nj < 4; nj++)
                    mma16816h(acc[mi][nj], a[mi], b[nj >> 1][(nj & 1) * 2],
                              b[nj >> 1][(nj & 1) * 2 + 1]);
        }
        __syncthreads();
        if (c + 2 <= 15) ISSUE(c & 1, (c + 2) * 64);
    }

    // ---- epilogue: stage u[64][128] (pad 132) + w2[128] + red[128][4] in smem
    float* su  = (float*)smem;                 // 33792 B
    float* sw2 = (float*)(smem + 33792);       // 512 B
    float* red = (float*)(smem + 34304);       // 2048 B
    for (int i = tid; i < 64 * 128; i += 256) {
        int b = i >> 7, n = i & 127;
        su[b * 132 + n] = g_u[b * H2 + n0 + n];
    }
    if (tid < 128) sw2[tid] = W2[n0 + tid];
    __syncthreads();

    {
        const int g = lane >> 2, t = lane & 3;
        float part[4][2];
#pragma unroll
        for (int mi = 0; mi < 4; mi++) { part[mi][0] = 0.f; part[mi][1] = 0.f; }

#pragma unroll
        for (int mi = 0; mi < 4; mi++) {
            int r_lo = wm * 64 + mi * 16 + g;
            int b_lo = r_lo & 63;
            int b_hi = (r_lo + 8) & 63;
#pragma unroll
            for (int nj = 0; nj < 4; nj++) {
                int n = wn * 32 + nj * 8 + 2 * t;
                float w0 = sw2[n], w1 = sw2[n + 1];
                float z00 = acc[mi][nj][0] + su[b_lo * 132 + n];
                float z01 = acc[mi][nj][1] + su[b_lo * 132 + n + 1];
                float z10 = acc[mi][nj][2] + su[b_hi * 132 + n];
                float z11 = acc[mi][nj][3] + su[b_hi * 132 + n + 1];
                part[mi][0] += w0 * tanh_ex(z00) + w1 * tanh_ex(z01);
                part[mi][1] += w0 * tanh_ex(z10) + w1 * tanh_ex(z11);
            }
        }
#pragma unroll
        for (int o = 1; o <= 2; o <<= 1)
#pragma unroll
            for (int mi = 0; mi < 4; mi++) {
                part[mi][0] += __shfl_xor_sync(0xffffffffu, part[mi][0], o);
                part[mi][1] += __shfl_xor_sync(0xffffffffu, part[mi][1], o);
            }
        if (t == 0) {
#pragma unroll
            for (int mi = 0; mi < 4; mi++) {
                red[(wm * 64 + mi * 16 + g) * 4 + wn]     = part[mi][0];
                red[(wm * 64 + mi * 16 + g + 8) * 4 + wn] = part[mi][1];
            }
        }
    }
    __syncthreads();

    if (tid < 128) {
        float s = red[tid * 4 + 0] + red[tid * 4 + 1] + red[tid * 4 + 2] + red[tid * 4 + 3];
        g_epart[(size_t)blockIdx.y * M_ROWS + m0 + tid] = s;
    }
}

// ---------------------------------------------------------------------------
// Kernel 4: softmax over s per batch -> alpha
// ---------------------------------------------------------------------------
__global__ void softmaxK(float* __restrict__ out) {
    int b = blockIdx.x;
    int s = threadIdx.x;
    float e = 0.f;
#pragma unroll
    for (int nt = 0; nt < NT2; nt++) e += g_epart[nt * M_ROWS + s * 64 + b];

    __shared__ float sm[512];
    sm[s] = e;
    __syncthreads();
    for (int off = 256; off > 0; off >>= 1) {
        if (s < off) sm[s] = fmaxf(sm[s], sm[s + off]);
        __syncthreads();
    }
    float mx = sm[0];
    __syncthreads();

    float ex = expf(e - mx);
    sm[s] = ex;
    __syncthreads();
    for (int off = 256; off > 0; off >>= 1) {
        if (s < off) sm[s] += sm[s + off];
        __syncthreads();
    }
    float total = sm[0];

    out[BATCH * H2 + b * SEQ + s] = ex / total;
}

// ---------------------------------------------------------------------------
// Kernel 5: context[b][h] = sum_s alpha[b][s] * enc[s][b][h]   (fp32 enc)
// ---------------------------------------------------------------------------
__global__ void contextK(const float* __restrict__ enc, float* __restrict__ out) {
    int b = blockIdx.y;
    int h = blockIdx.x * 256 + threadIdx.x;

    __shared__ float sa[512];
    sa[threadIdx.x]       = out[BATCH * H2 + b * SEQ + threadIdx.x];
    sa[threadIdx.x + 256] = out[BATCH * H2 + b * SEQ + threadIdx.x + 256];
    __syncthreads();

    const float* base = enc + b * H2 + h;
    float a0 = 0.f, a1 = 0.f, a2 = 0.f, a3 = 0.f;
#pragma unroll 4
    for (int s = 0; s < SEQ; s += 4) {
        a0 += sa[s + 0] * base[(size_t)(s + 0) * (BATCH * H2)];
        a1 += sa[s + 1] * base[(size_t)(s + 1) * (BATCH * H2)];
        a2 += sa[s + 2] * base[(size_t)(s + 2) * (BATCH * H2)];
        a3 += sa[s + 3] * base[(size_t)(s + 3) * (BATCH * H2)];
    }
    out[b * H2 + h] = (a0 + a1) + (a2 + a3);
}

// ---------------------------------------------------------------------------
extern "C" void kernel_launch(void* const* d_in, const int* in_sizes, int n_in,
                              void* d_out, int out_size) {
    const float* state = (const float*)d_in[0];
    const float* enc   = (const float*)d_in[1];
    const float* W1    = (const float*)d_in[2];
    const float* b1    = (const float*)d_in[3];
    const float* W2    = (const float*)d_in[4];
    float* out = (float*)d_out;

    cudaFuncSetAttribute(energyTC, cudaFuncAttributeMaxDynamicSharedMemorySize, EN_SMEM);

    convEnc<<<32768, 256>>>(enc);
    convW1<<<1024, 256>>>(W1);
    uGemm<<<dim3(16, KSPLIT), 256>>>(state, W1);
    reduceU<<<256, 256>>>(b1);
    energyTC<<<dim3(M_ROWS / 128, 8), 256, EN_SMEM>>>(W2);
    softmaxK<<<BATCH, 512>>>(out);
    contextK<<<dim3(4, BATCH), 256>>>(enc, out);
}

// round 6
// speedup vs baseline: 7.3954x; 1.4016x over previous
#include <cuda_runtime.h>
#include <cuda_fp16.h>
#include <cstdint>
#include <math.h>

// ---------------------------------------------------------------------------
// Problem constants
#define SEQ    512
#define BATCH  64
#define H2     1024
#define DIN    3072
#define KST    2048
#define M_ROWS (SEQ * BATCH)        // 32768
#define NT2    8                    // energy partial slabs (8 n-tiles of 128)
#define KSPLIT 8

// fp32 tiling for the small u GEMM
#define BM 64
#define BN 64
#define BK 16

// Scratch
__device__ __align__(16) float g_upart[KSPLIT * BATCH * H2];
__device__ __align__(16) float g_u[BATCH * H2];
__device__ __align__(16) float g_epart[NT2 * M_ROWS];
__device__ __align__(16) __half g_encH[M_ROWS * H2];   // 64 MB fp16 enc
__device__ __align__(16) __half g_w1H[H2 * H2];        // 2 MB  fp16 W1enc

// ---------------------------------------------------------------------------
// PTX helpers (base ISA only — compiles for sm_103)
// ---------------------------------------------------------------------------
__device__ __forceinline__ uint32_t smem_u32(const void* p) {
    uint32_t a;
    asm("{ .reg .u64 t; cvta.to.shared.u64 t, %1; cvt.u32.u64 %0, t; }" : "=r"(a) : "l"(p));
    return a;
}
// accurate tanh: 1 - 2/(exp2(2*log2e*x)+1)  (~1e-6 abs error)
__device__ __forceinline__ float tanh_ex(float x) {
    float t; asm("ex2.approx.f32 %0, %1;" : "=f"(t) : "f"(x * 2.8853900817779268f));
    float r; asm("rcp.approx.f32 %0, %1;" : "=f"(r) : "f"(t + 1.0f));
    return fmaf(-2.0f, r, 1.0f);
}

#define CP_ASYNC16(dst, src) \
    asm volatile("cp.async.cg.shared.global [%0], [%1], 16;" :: "r"(dst), "l"(src))
#define CP_COMMIT() asm volatile("cp.async.commit_group;" ::: "memory")
#define CP_WAIT2()  asm volatile("cp.async.wait_group 2;" ::: "memory")
#define CP_WAIT1()  asm volatile("cp.async.wait_group 1;" ::: "memory")
#define CP_WAIT0()  asm volatile("cp.async.wait_group 0;" ::: "memory")

__device__ __forceinline__ void ldsm4(uint32_t* d, uint32_t addr) {
    asm volatile("ldmatrix.sync.aligned.m8n8.x4.shared.b16 {%0,%1,%2,%3}, [%4];"
                 : "=r"(d[0]), "=r"(d[1]), "=r"(d[2]), "=r"(d[3]) : "r"(addr));
}
__device__ __forceinline__ void mma16816h(float* d, const uint32_t* a,
                                          uint32_t b0, uint32_t b1) {
    asm volatile("mma.sync.aligned.m16n8k16.row.col.f32.f16.f16.f32 "
                 "{%0,%1,%2,%3}, {%4,%5,%6,%7}, {%8,%9}, {%0,%1,%2,%3};"
                 : "+f"(d[0]), "+f"(d[1]), "+f"(d[2]), "+f"(d[3])
                 : "r"(a[0]), "r"(a[1]), "r"(a[2]), "r"(a[3]), "r"(b0), "r"(b1));
}

// ---------------------------------------------------------------------------
// Kernel A: enc fp32 -> fp16 (row-major 32768 x 1024)
// ---------------------------------------------------------------------------
__global__ void convEnc(const float* __restrict__ enc) {
    int idx = blockIdx.x * blockDim.x + threadIdx.x;      // 8388608 threads
    float4 v = *(const float4*)(enc + (size_t)idx * 4);
    __half2 h01 = __floats2half2_rn(v.x, v.y);
    __half2 h23 = __floats2half2_rn(v.z, v.w);
    *(uint2*)(g_encH + (size_t)idx * 4) =
        make_uint2(*(uint32_t*)&h01, *(uint32_t*)&h23);
}

// ---------------------------------------------------------------------------
// Kernel B: W1enc fp32 -> fp16 (1024 x 1024 slice at col offset KST)
// ---------------------------------------------------------------------------
__global__ void convW1(const float* __restrict__ W1) {
    int idx = blockIdx.x * blockDim.x + threadIdx.x;      // 262144 threads
    int n = idx >> 8;
    int k = (idx & 255) * 4;
    float4 v = *(const float4*)(W1 + (size_t)n * DIN + KST + k);
    __half2 hh0 = __floats2half2_rn(v.x, v.y);
    __half2 hh1 = __floats2half2_rn(v.z, v.w);
    *(uint2*)(g_w1H + (size_t)n * H2 + k) = make_uint2(*(uint32_t*)&hh0, *(uint32_t*)&hh1);
}

// ---------------------------------------------------------------------------
// Kernel 1: u partials (fp32; tiny).  Reads state directly (l = kd>>10).
// ---------------------------------------------------------------------------
__global__ void uGemm(const float* __restrict__ state, const float* __restrict__ W1) {
    const int n0 = blockIdx.x * BN;
    const int ks = blockIdx.y;
    const int k0base = ks * (KST / KSPLIT);

    __shared__ float As[BK][BM];
    __shared__ float Bs[BK][BN];

    const int tid = threadIdx.x;
    const int tx = tid & 15;
    const int ty = tid >> 4;
    const int lrow = tid >> 2;
    const int lcol = (tid & 3) * 4;

    float acc[4][4];
#pragma unroll
    for (int i = 0; i < 4; i++)
#pragma unroll
        for (int j = 0; j < 4; j++) acc[i][j] = 0.f;

    for (int k0 = k0base; k0 < k0base + (KST / KSPLIT); k0 += BK) {
        int kd = k0 + lcol;
        int l = kd >> 10, kk = kd & 1023;
        float4 a = *(const float4*)&state[((size_t)(l * 64 + lrow)) * 1024 + kk];
        float4 w = *(const float4*)&W1[(size_t)(n0 + lrow) * DIN + kd];
        As[lcol + 0][lrow] = a.x; As[lcol + 1][lrow] = a.y;
        As[lcol + 2][lrow] = a.z; As[lcol + 3][lrow] = a.w;
        Bs[lcol + 0][lrow] = w.x; Bs[lcol + 1][lrow] = w.y;
        Bs[lcol + 2][lrow] = w.z; Bs[lcol + 3][lrow] = w.w;
        __syncthreads();
#pragma unroll
        for (int kk2 = 0; kk2 < BK; kk2++) {
            float4 av = *(const float4*)&As[kk2][ty * 4];
            float4 bv = *(const float4*)&Bs[kk2][tx * 4];
            acc[0][0] += av.x * bv.x; acc[0][1] += av.x * bv.y; acc[0][2] += av.x * bv.z; acc[0][3] += av.x * bv.w;
            acc[1][0] += av.y * bv.x; acc[1][1] += av.y * bv.y; acc[1][2] += av.y * bv.z; acc[1][3] += av.y * bv.w;
            acc[2][0] += av.z * bv.x; acc[2][1] += av.z * bv.y; acc[2][2] += av.z * bv.z; acc[2][3] += av.z * bv.w;
            acc[3][0] += av.w * bv.x; acc[3][1] += av.w * bv.y; acc[3][2] += av.w * bv.z; acc[3][3] += av.w * bv.w;
        }
        __syncthreads();
    }

    float* dst = &g_upart[ks * (BATCH * H2)];
#pragma unroll
    for (int i = 0; i < 4; i++) {
        int b = ty * 4 + i;
#pragma unroll
        for (int j = 0; j < 4; j++) dst[b * H2 + n0 + tx * 4 + j] = acc[i][j];
    }
}

// ---------------------------------------------------------------------------
// Kernel 2: reduce split-K partials + bias -> g_u
// ---------------------------------------------------------------------------
__global__ void reduceU(const float* __restrict__ b1) {
    int idx = blockIdx.x * blockDim.x + threadIdx.x;
    int h = idx & 1023;
    float s = b1[h];
#pragma unroll
    for (int ks = 0; ks < KSPLIT; ks++) s += g_upart[ks * (BATCH * H2) + idx];
    g_u[idx] = s;
}

// ---------------------------------------------------------------------------
// Kernel 3: energy GEMM, fp16 single pass, fused tanh/W2 epilogue.
//
// CTA 128(M) x 128(N), 8 warps (2m x 4n), warp tile 64x32.
// K chunks of 64 fp16; 3-stage cp.async ring of preconverted fp16 tiles.
// Tiles: [128 rows][64 halfs] = 128B rows, swizzle group g^(r&7).
// Stage = A(16K) + B(16K) = 32K; 3 stages = 96K -> 2 CTA/SM (192K).
// ---------------------------------------------------------------------------
#define ST_A   0
#define ST_B   16384
#define ST_SZ  32768
#define EN_SMEM 98304

__device__ __forceinline__ uint32_t addrA(uint32_t tile, int R, int s, int lane) {
    int r = R + (lane & 15);
    int g = s * 2 + (lane >> 4);
    return tile + r * 128 + ((g ^ (r & 7)) << 4);
}
__device__ __forceinline__ uint32_t addrB(uint32_t tile, int N0, int s, int lane) {
    int n = N0 + (lane & 7) + ((lane >> 4) & 1) * 8;
    int g = s * 2 + ((lane >> 3) & 1);
    return tile + n * 128 + ((g ^ (n & 7)) << 4);
}

__global__ void __launch_bounds__(256, 2)
energyTC(const float* __restrict__ W2) {
    extern __shared__ char smem[];
    const uint32_t sb = smem_u32(smem);
    const int tid = threadIdx.x;
    const int wid = tid >> 5;
    const int lane = tid & 31;
    const int wm = wid >> 2;      // 0..1
    const int wn = wid & 3;       // 0..3
    const int m0 = blockIdx.x * 128;
    const int n0 = blockIdx.y * 128;

    float acc[4][4][4];
#pragma unroll
    for (int i = 0; i < 4; i++)
#pragma unroll
        for (int j = 0; j < 4; j++)
#pragma unroll
            for (int k = 0; k < 4; k++) acc[i][j][k] = 0.f;

    const int r_ld = tid >> 3;        // base row 0..31; r = r_ld + t*32
    const int g_ld = tid & 7;         // 16B group 0..7

    // stage issue: 8 cp.async per thread (4 A + 4 B)
#define ISSUE(stg, k0)                                                          \
    do {                                                                        \
        uint32_t _s = sb + (stg) * ST_SZ;                                       \
        _Pragma("unroll")                                                       \
        for (int t = 0; t < 4; t++) {                                           \
            int r = r_ld + t * 32;                                              \
            uint32_t sw = ((g_ld ^ (r & 7)) << 4);                              \
            CP_ASYNC16(_s + ST_A + r * 128 + sw,                                \
                       g_encH + (size_t)(m0 + r) * H2 + (k0) + g_ld * 8);       \
            CP_ASYNC16(_s + ST_B + r * 128 + sw,                                \
                       g_w1H + (size_t)(n0 + r) * H2 + (k0) + g_ld * 8);        \
        }                                                                       \
        CP_COMMIT();                                                            \
    } while (0)

    ISSUE(0, 0);
    ISSUE(1, 64);

    for (int c = 0; c < 16; c++) {
        if (c + 2 <= 15) {
            ISSUE((c + 2) % 3, (c + 2) * 64);   // overwrites stage used at c-1
            CP_WAIT2();
        } else if (c + 1 <= 15) {
            CP_WAIT1();
        } else {
            CP_WAIT0();
        }
        __syncthreads();

        const uint32_t stg = sb + (c % 3) * ST_SZ;
        const uint32_t tA = stg + ST_A, tB = stg + ST_B;

#pragma unroll
        for (int s = 0; s < 4; s++) {
            uint32_t a[4][4], b[2][4];
#pragma unroll
            for (int mi = 0; mi < 4; mi++)
                ldsm4(a[mi], addrA(tA, wm * 64 + mi * 16, s, lane));
            ldsm4(b[0], addrB(tB, wn * 32, s, lane));
            ldsm4(b[1], addrB(tB, wn * 32 + 16, s, lane));
#pragma unroll
            for (int mi = 0; mi < 4; mi++)
#pragma unroll
                for (int nj = 0; nj < 4; nj++)
                    mma16816h(acc[mi][nj], a[mi], b[nj >> 1][(nj & 1) * 2],
                              b[nj >> 1][(nj & 1) * 2 + 1]);
        }
        __syncthreads();
    }

    // ---- epilogue: stage u[64][128] (pad 132) + w2[128] + red[128][4] in smem
    float* su  = (float*)smem;                 // 33792 B
    float* sw2 = (float*)(smem + 33792);       // 512 B
    float* red = (float*)(smem + 34304);       // 2048 B
    for (int i = tid; i < 64 * 128; i += 256) {
        int b = i >> 7, n = i & 127;
        su[b * 132 + n] = g_u[b * H2 + n0 + n];
    }
    if (tid < 128) sw2[tid] = W2[n0 + tid];
    __syncthreads();

    {
        const int g = lane >> 2, t = lane & 3;
        float part[4][2];
#pragma unroll
        for (int mi = 0; mi < 4; mi++) { part[mi][0] = 0.f; part[mi][1] = 0.f; }

#pragma unroll
        for (int mi = 0; mi < 4; mi++) {
            int r_lo = wm * 64 + mi * 16 + g;
            int b_lo = r_lo & 63;
            int b_hi = (r_lo + 8) & 63;
#pragma unroll
            for (int nj = 0; nj < 4; nj++) {
                int n = wn * 32 + nj * 8 + 2 * t;
                float w0 = sw2[n], w1 = sw2[n + 1];
                float z00 = acc[mi][nj][0] + su[b_lo * 132 + n];
                float z01 = acc[mi][nj][1] + su[b_lo * 132 + n + 1];
                float z10 = acc[mi][nj][2] + su[b_hi * 132 + n];
                float z11 = acc[mi][nj][3] + su[b_hi * 132 + n + 1];
                part[mi][0] += w0 * tanh_ex(z00) + w1 * tanh_ex(z01);
                part[mi][1] += w0 * tanh_ex(z10) + w1 * tanh_ex(z11);
            }
        }
#pragma unroll
        for (int o = 1; o <= 2; o <<= 1)
#pragma unroll
            for (int mi = 0; mi < 4; mi++) {
                part[mi][0] += __shfl_xor_sync(0xffffffffu, part[mi][0], o);
                part[mi][1] += __shfl_xor_sync(0xffffffffu, part[mi][1], o);
            }
        if (t == 0) {
#pragma unroll
            for (int mi = 0; mi < 4; mi++) {
                red[(wm * 64 + mi * 16 + g) * 4 + wn]     = part[mi][0];
                red[(wm * 64 + mi * 16 + g + 8) * 4 + wn] = part[mi][1];
            }
        }
    }
    __syncthreads();

    if (tid < 128) {
        float s = red[tid * 4 + 0] + red[tid * 4 + 1] + red[tid * 4 + 2] + red[tid * 4 + 3];
        g_epart[(size_t)blockIdx.y * M_ROWS + m0 + tid] = s;
    }
}

// ---------------------------------------------------------------------------
// Kernel 4: softmax over s per batch -> alpha
// ---------------------------------------------------------------------------
__global__ void softmaxK(float* __restrict__ out) {
    int b = blockIdx.x;
    int s = threadIdx.x;
    float e = 0.f;
#pragma unroll
    for (int nt = 0; nt < NT2; nt++) e += g_epart[nt * M_ROWS + s * 64 + b];

    __shared__ float sm[512];
    sm[s] = e;
    __syncthreads();
    for (int off = 256; off > 0; off >>= 1) {
        if (s < off) sm[s] = fmaxf(sm[s], sm[s + off]);
        __syncthreads();
    }
    float mx = sm[0];
    __syncthreads();

    float ex = expf(e - mx);
    sm[s] = ex;
    __syncthreads();
    for (int off = 256; off > 0; off >>= 1) {
        if (s < off) sm[s] += sm[s + off];
        __syncthreads();
    }
    float total = sm[0];

    out[BATCH * H2 + b * SEQ + s] = ex / total;
}

// ---------------------------------------------------------------------------
// Kernel 5: context[b][h] = sum_s alpha[b][s] * enc[s][b][h]   (fp32 enc)
// ---------------------------------------------------------------------------
__global__ void contextK(const float* __restrict__ enc, float* __restrict__ out) {
    int b = blockIdx.y;
    int h = blockIdx.x * 256 + threadIdx.x;

    __shared__ float sa[512];
    sa[threadIdx.x]       = out[BATCH * H2 + b * SEQ + threadIdx.x];
    sa[threadIdx.x + 256] = out[BATCH * H2 + b * SEQ + threadIdx.x + 256];
    __syncthreads();

    const float* base = enc + b * H2 + h;
    float a0 = 0.f, a1 = 0.f, a2 = 0.f, a3 = 0.f;
#pragma unroll 4
    for (int s = 0; s < SEQ; s += 4) {
        a0 += sa[s + 0] * base[(size_t)(s + 0) * (BATCH * H2)];
        a1 += sa[s + 1] * base[(size_t)(s + 1) * (BATCH * H2)];
        a2 += sa[s + 2] * base[(size_t)(s + 2) * (BATCH * H2)];
        a3 += sa[s + 3] * base[(size_t)(s + 3) * (BATCH * H2)];
    }
    out[b * H2 + h] = (a0 + a1) + (a2 + a3);
}

// ---------------------------------------------------------------------------
extern "C" void kernel_launch(void* const* d_in, const int* in_sizes, int n_in,
                              void* d_out, int out_size) {
    const float* state = (const float*)d_in[0];
    const float* enc   = (const float*)d_in[1];
    const float* W1    = (const float*)d_in[2];
    const float* b1    = (const float*)d_in[3];
    const float* W2    = (const float*)d_in[4];
    float* out = (float*)d_out;

    cudaFuncSetAttribute(energyTC, cudaFuncAttributeMaxDynamicSharedMemorySize, EN_SMEM);

    convEnc<<<32768, 256>>>(enc);
    convW1<<<1024, 256>>>(W1);
    uGemm<<<dim3(16, KSPLIT), 256>>>(state, W1);
    reduceU<<<256, 256>>>(b1);
    energyTC<<<dim3(M_ROWS / 128, 8), 256, EN_SMEM>>>(W2);
    softmaxK<<<BATCH, 512>>>(out);
    contextK<<<dim3(4, BATCH), 256>>>(enc, out);
}

// round 7
// speedup vs baseline: 8.0909x; 1.0940x over previous
#include <cuda_runtime.h>
#include <cuda_fp16.h>
#include <cstdint>
#include <math.h>

// ---------------------------------------------------------------------------
// Problem constants
#define SEQ    512
#define BATCH  64
#define H2     1024
#define DIN    3072
#define KST    2048
#define M_ROWS (SEQ * BATCH)        // 32768
#define NT2    8                    // energy partial slabs (8 n-tiles of 128)
#define KSPLIT 16

// fp32 tiling for the small u GEMM
#define BM 64
#define BN 64
#define BK 16

// Scratch
__device__ __align__(16) float g_upart[KSPLIT * BATCH * H2];
__device__ __align__(16) float g_u[BATCH * H2];
__device__ __align__(16) float g_epart[NT2 * M_ROWS];
__device__ __align__(16) __half g_encH[M_ROWS * H2];   // 64 MB fp16 enc
__device__ __align__(16) __half g_w1H[H2 * H2];        // 2 MB  fp16 W1enc

// ---------------------------------------------------------------------------
// PTX helpers (base ISA only — compiles for sm_103)
// ---------------------------------------------------------------------------
__device__ __forceinline__ uint32_t smem_u32(const void* p) {
    uint32_t a;
    asm("{ .reg .u64 t; cvta.to.shared.u64 t, %1; cvt.u32.u64 %0, t; }" : "=r"(a) : "l"(p));
    return a;
}
// accurate tanh: 1 - 2/(exp2(2*log2e*x)+1)  (~1e-6 abs error)
__device__ __forceinline__ float tanh_ex(float x) {
    float t; asm("ex2.approx.f32 %0, %1;" : "=f"(t) : "f"(x * 2.8853900817779268f));
    float r; asm("rcp.approx.f32 %0, %1;" : "=f"(r) : "f"(t + 1.0f));
    return fmaf(-2.0f, r, 1.0f);
}

#define CP_ASYNC16(dst, src) \
    asm volatile("cp.async.cg.shared.global [%0], [%1], 16;" :: "r"(dst), "l"(src))
#define CP_COMMIT() asm volatile("cp.async.commit_group;" ::: "memory")
#define CP_WAIT1()  asm volatile("cp.async.wait_group 1;" ::: "memory")
#define CP_WAIT0()  asm volatile("cp.async.wait_group 0;" ::: "memory")

__device__ __forceinline__ void ldsm4(uint32_t* d, uint32_t addr) {
    asm volatile("ldmatrix.sync.aligned.m8n8.x4.shared.b16 {%0,%1,%2,%3}, [%4];"
                 : "=r"(d[0]), "=r"(d[1]), "=r"(d[2]), "=r"(d[3]) : "r"(addr));
}
__device__ __forceinline__ void mma16816h(float* d, const uint32_t* a,
                                          uint32_t b0, uint32_t b1) {
    asm volatile("mma.sync.aligned.m16n8k16.row.col.f32.f16.f16.f32 "
                 "{%0,%1,%2,%3}, {%4,%5,%6,%7}, {%8,%9}, {%0,%1,%2,%3};"
                 : "+f"(d[0]), "+f"(d[1]), "+f"(d[2]), "+f"(d[3])
                 : "r"(a[0]), "r"(a[1]), "r"(a[2]), "r"(a[3]), "r"(b0), "r"(b1));
}

// ---------------------------------------------------------------------------
// Kernel A: fused fp32->fp16 conversion of enc (32768x1024) and W1enc (1024x1024)
// ---------------------------------------------------------------------------
__global__ void convAll(const float* __restrict__ enc, const float* __restrict__ W1) {
    int bid = blockIdx.x;
    if (bid < 32768) {
        int idx = bid * 256 + threadIdx.x;
        float4 v = *(const float4*)(enc + (size_t)idx * 4);
        __half2 h01 = __floats2half2_rn(v.x, v.y);
        __half2 h23 = __floats2half2_rn(v.z, v.w);
        *(uint2*)(g_encH + (size_t)idx * 4) =
            make_uint2(*(uint32_t*)&h01, *(uint32_t*)&h23);
    } else {
        int idx = (bid - 32768) * 256 + threadIdx.x;   // 0..262143
        int n = idx >> 8;
        int k = (idx & 255) * 4;
        float4 v = *(const float4*)(W1 + (size_t)n * DIN + KST + k);
        __half2 hh0 = __floats2half2_rn(v.x, v.y);
        __half2 hh1 = __floats2half2_rn(v.z, v.w);
        *(uint2*)(g_w1H + (size_t)n * H2 + k) =
            make_uint2(*(uint32_t*)&hh0, *(uint32_t*)&hh1);
    }
}

// ---------------------------------------------------------------------------
// Kernel 1: u partials (fp32; tiny).  Reads state directly (l = kd>>10).
// ---------------------------------------------------------------------------
__global__ void uGemm(const float* __restrict__ state, const float* __restrict__ W1) {
    const int n0 = blockIdx.x * BN;
    const int ks = blockIdx.y;
    const int k0base = ks * (KST / KSPLIT);

    __shared__ float As[BK][BM];
    __shared__ float Bs[BK][BN];

    const int tid = threadIdx.x;
    const int tx = tid & 15;
    const int ty = tid >> 4;
    const int lrow = tid >> 2;
    const int lcol = (tid & 3) * 4;

    float acc[4][4];
#pragma unroll
    for (int i = 0; i < 4; i++)
#pragma unroll
        for (int j = 0; j < 4; j++) acc[i][j] = 0.f;

    for (int k0 = k0base; k0 < k0base + (KST / KSPLIT); k0 += BK) {
        int kd = k0 + lcol;
        int l = kd >> 10, kk = kd & 1023;
        float4 a = *(const float4*)&state[((size_t)(l * 64 + lrow)) * 1024 + kk];
        float4 w = *(const float4*)&W1[(size_t)(n0 + lrow) * DIN + kd];
        As[lcol + 0][lrow] = a.x; As[lcol + 1][lrow] = a.y;
        As[lcol + 2][lrow] = a.z; As[lcol + 3][lrow] = a.w;
        Bs[lcol + 0][lrow] = w.x; Bs[lcol + 1][lrow] = w.y;
        Bs[lcol + 2][lrow] = w.z; Bs[lcol + 3][lrow] = w.w;
        __syncthreads();
#pragma unroll
        for (int kk2 = 0; kk2 < BK; kk2++) {
            float4 av = *(const float4*)&As[kk2][ty * 4];
            float4 bv = *(const float4*)&Bs[kk2][tx * 4];
            acc[0][0] += av.x * bv.x; acc[0][1] += av.x * bv.y; acc[0][2] += av.x * bv.z; acc[0][3] += av.x * bv.w;
            acc[1][0] += av.y * bv.x; acc[1][1] += av.y * bv.y; acc[1][2] += av.y * bv.z; acc[1][3] += av.y * bv.w;
            acc[2][0] += av.z * bv.x; acc[2][1] += av.z * bv.y; acc[2][2] += av.z * bv.z; acc[2][3] += av.z * bv.w;
            acc[3][0] += av.w * bv.x; acc[3][1] += av.w * bv.y; acc[3][2] += av.w * bv.z; acc[3][3] += av.w * bv.w;
        }
        __syncthreads();
    }

    float* dst = &g_upart[ks * (BATCH * H2)];
#pragma unroll
    for (int i = 0; i < 4; i++) {
        int b = ty * 4 + i;
#pragma unroll
        for (int j = 0; j < 4; j++) dst[b * H2 + n0 + tx * 4 + j] = acc[i][j];
    }
}

// ---------------------------------------------------------------------------
// Kernel 2: reduce split-K partials + bias -> g_u
// ---------------------------------------------------------------------------
__global__ void reduceU(const float* __restrict__ b1) {
    int idx = blockIdx.x * blockDim.x + threadIdx.x;
    int h = idx & 1023;
    float s = b1[h];
#pragma unroll
    for (int ks = 0; ks < KSPLIT; ks++) s += g_upart[ks * (BATCH * H2) + idx];
    g_u[idx] = s;
}

// ---------------------------------------------------------------------------
// Kernel 3: energy GEMM, fp16 single pass, single-sync 3-stage pipeline,
//           fused tanh/W2 epilogue.
// CTA 128(M) x 128(N), 8 warps (2m x 4n), warp tile 64x32.
// Stage = A(16K) + B(16K) = 32K; 3 stages = 96K -> 2 CTA/SM.
// ---------------------------------------------------------------------------
#define ST_A   0
#define ST_B   16384
#define ST_SZ  32768
#define EN_SMEM 98304

__device__ __forceinline__ uint32_t addrA(uint32_t tile, int R, int s, int lane) {
    int r = R + (lane & 15);
    int g = s * 2 + (lane >> 4);
    return tile + r * 128 + ((g ^ (r & 7)) << 4);
}
__device__ __forceinline__ uint32_t addrB(uint32_t tile, int N0, int s, int lane) {
    int n = N0 + (lane & 7) + ((lane >> 4) & 1) * 8;
    int g = s * 2 + ((lane >> 3) & 1);
    return tile + n * 128 + ((g ^ (n & 7)) << 4);
}

__global__ void __launch_bounds__(256, 2)
energyTC(const float* __restrict__ W2) {
    extern __shared__ char smem[];
    const uint32_t sb = smem_u32(smem);
    const int tid = threadIdx.x;
    const int wid = tid >> 5;
    const int lane = tid & 31;
    const int wm = wid >> 2;      // 0..1
    const int wn = wid & 3;       // 0..3
    const int m0 = blockIdx.x * 128;
    const int n0 = blockIdx.y * 128;

    float acc[4][4][4];
#pragma unroll
    for (int i = 0; i < 4; i++)
#pragma unroll
        for (int j = 0; j < 4; j++)
#pragma unroll
            for (int k = 0; k < 4; k++) acc[i][j][k] = 0.f;

    const int r_ld = tid >> 3;        // base row 0..31; r = r_ld + t*32
    const int g_ld = tid & 7;         // 16B group 0..7

#define ISSUE(stg, k0)                                                          \
    do {                                                                        \
        uint32_t _s = sb + (stg) * ST_SZ;                                       \
        _Pragma("unroll")                                                       \
        for (int t = 0; t < 4; t++) {                                           \
            int r = r_ld + t * 32;                                              \
            uint32_t sw = ((g_ld ^ (r & 7)) << 4);                              \
            CP_ASYNC16(_s + ST_A + r * 128 + sw,                                \
                       g_encH + (size_t)(m0 + r) * H2 + (k0) + g_ld * 8);       \
            CP_ASYNC16(_s + ST_B + r * 128 + sw,                                \
                       g_w1H + (size_t)(n0 + r) * H2 + (k0) + g_ld * 8);        \
        }                                                                       \
        CP_COMMIT();                                                            \
    } while (0)

    ISSUE(0, 0);
    ISSUE(1, 64);

    for (int c = 0; c < 16; c++) {
        // chunk c's group completes: in flight are chunks c, c+1 -> wait<=1
        if (c < 15) CP_WAIT1(); else CP_WAIT0();
        __syncthreads();   // (a) chunk-c data visible to all warps
                           // (b) all warps finished reading stage (c-1)%3
        if (c + 2 <= 15) ISSUE((c + 2) % 3, (c + 2) * 64);  // overwrites (c-1)%3

        const uint32_t stg = sb + (c % 3) * ST_SZ;
        const uint32_t tA = stg + ST_A, tB = stg + ST_B;

#pragma unroll
        for (int s = 0; s < 4; s++) {
            uint32_t a[4][4], b[2][4];
#pragma unroll
            for (int mi = 0; mi < 4; mi++)
                ldsm4(a[mi], addrA(tA, wm * 64 + mi * 16, s, lane));
            ldsm4(b[0], addrB(tB, wn * 32, s, lane));
            ldsm4(b[1], addrB(tB, wn * 32 + 16, s, lane));
#pragma unroll
            for (int mi = 0; mi < 4; mi++)
#pragma unroll
                for (int nj = 0; nj < 4; nj++)
                    mma16816h(acc[mi][nj], a[mi], b[nj >> 1][(nj & 1) * 2],
                              b[nj >> 1][(nj & 1) * 2 + 1]);
        }
    }
    __syncthreads();   // all warps done with stages before su overwrites them

    // ---- epilogue: stage u[64][128] (pad 132) + w2[128] + red[128][4] in smem
    float* su  = (float*)smem;                 // 33792 B
    float* sw2 = (float*)(smem + 33792);       // 512 B
    float* red = (float*)(smem + 34304);       // 2048 B
    for (int i = tid; i < 64 * 128; i += 256) {
        int b = i >> 7, n = i & 127;
        su[b * 132 + n] = g_u[b * H2 + n0 + n];
    }
    if (tid < 128) sw2[tid] = W2[n0 + tid];
    __syncthreads();

    {
        const int g = lane >> 2, t = lane & 3;
        float part[4][2];
#pragma unroll
        for (int mi = 0; mi < 4; mi++) { part[mi][0] = 0.f; part[mi][1] = 0.f; }

#pragma unroll
        for (int mi = 0; mi < 4; mi++) {
            int r_lo = wm * 64 + mi * 16 + g;
            int b_lo = r_lo & 63;
            int b_hi = (r_lo + 8) & 63;
#pragma unroll
            for (int nj = 0; nj < 4; nj++) {
                int n = wn * 32 + nj * 8 + 2 * t;
                float w0 = sw2[n], w1 = sw2[n + 1];
                float z00 = acc[mi][nj][0] + su[b_lo * 132 + n];
                float z01 = acc[mi][nj][1] + su[b_lo * 132 + n + 1];
                float z10 = acc[mi][nj][2] + su[b_hi * 132 + n];
                float z11 = acc[mi][nj][3] + su[b_hi * 132 + n + 1];
                part[mi][0] += w0 * tanh_ex(z00) + w1 * tanh_ex(z01);
                part[mi][1] += w0 * tanh_ex(z10) + w1 * tanh_ex(z11);
            }
        }
#pragma unroll
        for (int o = 1; o <= 2; o <<= 1)
#pragma unroll
            for (int mi = 0; mi < 4; mi++) {
                part[mi][0] += __shfl_xor_sync(0xffffffffu, part[mi][0], o);
                part[mi][1] += __shfl_xor_sync(0xffffffffu, part[mi][1], o);
            }
        if (t == 0) {
#pragma unroll
            for (int mi = 0; mi < 4; mi++) {
                red[(wm * 64 + mi * 16 + g) * 4 + wn]     = part[mi][0];
                red[(wm * 64 + mi * 16 + g + 8) * 4 + wn] = part[mi][1];
            }
        }
    }
    __syncthreads();

    if (tid < 128) {
        float s = red[tid * 4 + 0] + red[tid * 4 + 1] + red[tid * 4 + 2] + red[tid * 4 + 3];
        g_epart[(size_t)blockIdx.y * M_ROWS + m0 + tid] = s;
    }
}

// ---------------------------------------------------------------------------
// Kernel 4: softmax over s per batch -> alpha
// ---------------------------------------------------------------------------
__global__ void softmaxK(float* __restrict__ out) {
    int b = blockIdx.x;
    int s = threadIdx.x;
    float e = 0.f;
#pragma unroll
    for (int nt = 0; nt < NT2; nt++) e += g_epart[nt * M_ROWS + s * 64 + b];

    __shared__ float sm[512];
    sm[s] = e;
    __syncthreads();
    for (int off = 256; off > 0; off >>= 1) {
        if (s < off) sm[s] = fmaxf(sm[s], sm[s + off]);
        __syncthreads();
    }
    float mx = sm[0];
    __syncthreads();

    float ex = expf(e - mx);
    sm[s] = ex;
    __syncthreads();
    for (int off = 256; off > 0; off >>= 1) {
        if (s < off) sm[s] += sm[s + off];
        __syncthreads();
    }
    float total = sm[0];

    out[BATCH * H2 + b * SEQ + s] = ex / total;
}

// ---------------------------------------------------------------------------
// Kernel 5: context[b][h] = sum_s alpha[b][s] * enc[s][b][h]  (fp16 enc, fp32 math)
// grid = (2 h2-chunks, 64 b), 256 threads; each thread one __half2 column pair.
// ---------------------------------------------------------------------------
__global__ void contextK(float* __restrict__ out) {
    int b = blockIdx.y;
    int hp = blockIdx.x * 256 + threadIdx.x;    // half2 index 0..511

    __shared__ float sa[512];
    sa[threadIdx.x]       = out[BATCH * H2 + b * SEQ + threadIdx.x];
    sa[threadIdx.x + 256] = out[BATCH * H2 + b * SEQ + threadIdx.x + 256];
    __syncthreads();

    const __half2* base = (const __half2*)g_encH + (size_t)b * 512 + hp;
    float2 a0 = {0.f, 0.f}, a1 = {0.f, 0.f}, a2 = {0.f, 0.f}, a3 = {0.f, 0.f};
#pragma unroll 4
    for (int s = 0; s < SEQ; s += 4) {
        float2 f0 = __half22float2(base[(size_t)(s + 0) * (BATCH * 512)]);
        float2 f1 = __half22float2(base[(size_t)(s + 1) * (BATCH * 512)]);
        float2 f2 = __half22float2(base[(size_t)(s + 2) * (BATCH * 512)]);
        float2 f3 = __half22float2(base[(size_t)(s + 3) * (BATCH * 512)]);
        a0.x += sa[s + 0] * f0.x; a0.y += sa[s + 0] * f0.y;
        a1.x += sa[s + 1] * f1.x; a1.y += sa[s + 1] * f1.y;
        a2.x += sa[s + 2] * f2.x; a2.y += sa[s + 2] * f2.y;
        a3.x += sa[s + 3] * f3.x; a3.y += sa[s + 3] * f3.y;
    }
    float rx = (a0.x + a1.x) + (a2.x + a3.x);
    float ry = (a0.y + a1.y) + (a2.y + a3.y);
    out[b * H2 + hp * 2]     = rx;
    out[b * H2 + hp * 2 + 1] = ry;
}

// ---------------------------------------------------------------------------
extern "C" void kernel_launch(void* const* d_in, const int* in_sizes, int n_in,
                              void* d_out, int out_size) {
    const float* state = (const float*)d_in[0];
    const float* enc   = (const float*)d_in[1];
    const float* W1    = (const float*)d_in[2];
    const float* b1    = (const float*)d_in[3];
    const float* W2    = (const float*)d_in[4];
    float* out = (float*)d_out;

    cudaFuncSetAttribute(energyTC, cudaFuncAttributeMaxDynamicSharedMemorySize, EN_SMEM);

    convAll<<<33792, 256>>>(enc, W1);
    uGemm<<<dim3(16, KSPLIT), 256>>>(state, W1);
    reduceU<<<256, 256>>>(b1);
    energyTC<<<dim3(M_ROWS / 128, 8), 256, EN_SMEM>>>(W2);
    softmaxK<<<BATCH, 512>>>(out);
    contextK<<<dim3(2, BATCH), 256>>>(out);
}